// round 2
// baseline (speedup 1.0000x reference)
#include <cuda_runtime.h>
#include <cuda_bf16.h>
#include <cstdint>

#define NN 100000
#define NE 1600000
#define DD 128
#define LL 3

// ---------------- device scratch (static allocation, allowed) ----------------
__device__ float g_hA[(size_t)NN * DD];
__device__ float g_hB[(size_t)NN * DD];
__device__ float g_inv[NN];
__device__ int   g_deg[NN];
__device__ int   g_off[NN + 1];
__device__ int   g_cur[NN];
__device__ int   g_csr[NE];

// ---------------- setup: hA = emb[annotation], zero deg ----------------
__global__ void k_init(const int* __restrict__ ann, const float* __restrict__ emb) {
    int t = blockIdx.x * blockDim.x + threadIdx.x;
    if (t < NN * 32) {
        int v = t >> 5, lane = t & 31;
        int a = ann[v];
        ((float4*)g_hA)[t] = ((const float4*)emb)[(size_t)a * 32 + lane];
    }
    if (t < NN) g_deg[t] = 0;
}

// ---------------- degree count ----------------
__global__ void k_count(const int* __restrict__ dst) {
    int e = blockIdx.x * blockDim.x + threadIdx.x;
    if (e < NE) atomicAdd(&g_deg[dst[e]], 1);
}

// ---------------- fast single-block scan: range-per-thread + shuffle scan ----------------
__global__ void __launch_bounds__(1024) k_scan() {
    const int PER = (NN + 1023) / 1024;     // 98
    int t = threadIdx.x;
    int lo = t * PER;
    int hi = lo + PER; if (hi > NN) hi = NN;
    int s = 0;
    for (int i = lo; i < hi; i++) s += g_deg[i];

    // block exclusive scan of s
    int lane = t & 31, w = t >> 5;
    int v = s;
    #pragma unroll
    for (int o = 1; o < 32; o <<= 1) {
        int u = __shfl_up_sync(0xffffffffu, v, o);
        if (lane >= o) v += u;
    }
    __shared__ int ws[32];
    if (lane == 31) ws[w] = v;
    __syncthreads();
    if (w == 0) {
        int x = ws[lane];
        #pragma unroll
        for (int o = 1; o < 32; o <<= 1) {
            int u = __shfl_up_sync(0xffffffffu, x, o);
            if (lane >= o) x += u;
        }
        ws[lane] = x;
    }
    __syncthreads();
    int ex = v - s + (w > 0 ? ws[w - 1] : 0);

    int run = ex;
    for (int i = lo; i < hi; i++) {
        int d = g_deg[i];
        g_off[i] = run;
        g_cur[i] = run;
        g_inv[i] = 1.0f / (float)(d + 1);
        run += d;
    }
    if (hi == NN && lo < NN) g_off[NN] = run;
    if (t == 1023 && lo >= NN) g_off[NN] = NE;  // safety (not hit with PER=98)
}

// ---------------- scatter edges into CSR (grouped by dst) ----------------
__global__ void k_scatter(const int* __restrict__ src, const int* __restrict__ dst) {
    int e = blockIdx.x * blockDim.x + threadIdx.x;
    if (e < NE) {
        int d = dst[e];
        int p = atomicAdd(&g_cur[d], 1);
        g_csr[p] = src[e];
    }
}

// ---------------- fused layer: aggregate -> tf32 mma -> bias+relu ----------------
#define APITCH 132   // A tile pitch in words: bank = (4r + c) & 31, conflict-free
#define BPITCH 136   // B tile pitch in words: bank = (8k + n) & 31, conflict-free
#define LSMEM ((128 * APITCH + 128 * BPITCH) * 4)

__device__ __forceinline__ uint32_t f2tf32(float f) {
    uint32_t u;
    asm("cvt.rna.tf32.f32 %0, %1;" : "=r"(u) : "f"(f));
    return u;
}

__global__ void __launch_bounds__(256) k_layer(const float* __restrict__ hin,
                                               float* __restrict__ hout,
                                               const float* __restrict__ W,
                                               const float* __restrict__ bias) {
    extern __shared__ uint32_t sm[];
    uint32_t* As = sm;                 // [128][APITCH] tf32
    uint32_t* Bs = sm + 128 * APITCH;  // [128][BPITCH] tf32, Bs[k][n]
    int tid = threadIdx.x;
    int lane = tid & 31, w = tid >> 5;
    int m0 = blockIdx.x * 128;

    // ---- phase 1a: load W -> Bs (tf32) ----
    #pragma unroll
    for (int t = 0; t < 16; t++) {
        int q = tid + t * 256;            // 0..4095 float4s
        int r = q >> 5, c4 = (q & 31) * 4;
        float4 v = ((const float4*)W)[q];
        uint32_t* p = &Bs[r * BPITCH + c4];
        p[0] = f2tf32(v.x); p[1] = f2tf32(v.y); p[2] = f2tf32(v.z); p[3] = f2tf32(v.w);
    }

    // ---- phase 1b: aggregate 16 nodes per warp -> As (tf32) ----
    const float4* h4 = (const float4*)hin;
    for (int i = 0; i < 16; i++) {
        int r = w * 16 + i;
        int v = m0 + r;
        float4 acc = make_float4(0.f, 0.f, 0.f, 0.f);
        if (v < NN) {
            acc = h4[(size_t)v * 32 + lane];
            int s = g_off[v], e = g_off[v + 1];
            for (int j = s; j < e; j++) {
                int u = __ldg(&g_csr[j]);
                float4 x = h4[(size_t)u * 32 + lane];
                acc.x += x.x; acc.y += x.y; acc.z += x.z; acc.w += x.w;
            }
            float iv = g_inv[v];
            acc.x *= iv; acc.y *= iv; acc.z *= iv; acc.w *= iv;
        }
        uint4 tv;
        tv.x = f2tf32(acc.x); tv.y = f2tf32(acc.y); tv.z = f2tf32(acc.z); tv.w = f2tf32(acc.w);
        *(uint4*)&As[r * APITCH + lane * 4] = tv;
    }
    __syncthreads();

    // ---- phase 2: tf32 mma, warp tile 32(M) x 64(N) ----
    int warp_m = w >> 1;          // 0..3
    int warp_n = w & 1;           // 0..1
    int g = lane >> 2;            // groupID 0..7
    int tg = lane & 3;            // threadID in group 0..3

    float acc[2][8][4];
    #pragma unroll
    for (int mi = 0; mi < 2; mi++)
        #pragma unroll
        for (int ni = 0; ni < 8; ni++)
            #pragma unroll
            for (int c = 0; c < 4; c++) acc[mi][ni][c] = 0.f;

    #pragma unroll
    for (int kc = 0; kc < 16; kc++) {
        int k0 = kc * 8;
        uint32_t a[2][4];
        #pragma unroll
        for (int mi = 0; mi < 2; mi++) {
            int r = warp_m * 32 + mi * 16 + g;
            a[mi][0] = As[r * APITCH + k0 + tg];
            a[mi][1] = As[(r + 8) * APITCH + k0 + tg];
            a[mi][2] = As[r * APITCH + k0 + tg + 4];
            a[mi][3] = As[(r + 8) * APITCH + k0 + tg + 4];
        }
        #pragma unroll
        for (int ni = 0; ni < 8; ni++) {
            int cn = warp_n * 64 + ni * 8 + g;
            uint32_t b0 = Bs[(k0 + tg) * BPITCH + cn];
            uint32_t b1 = Bs[(k0 + tg + 4) * BPITCH + cn];
            #pragma unroll
            for (int mi = 0; mi < 2; mi++) {
                asm volatile(
                    "mma.sync.aligned.m16n8k8.row.col.f32.tf32.tf32.f32 "
                    "{%0,%1,%2,%3}, {%4,%5,%6,%7}, {%8,%9}, {%0,%1,%2,%3};"
                    : "+f"(acc[mi][ni][0]), "+f"(acc[mi][ni][1]),
                      "+f"(acc[mi][ni][2]), "+f"(acc[mi][ni][3])
                    : "r"(a[mi][0]), "r"(a[mi][1]), "r"(a[mi][2]), "r"(a[mi][3]),
                      "r"(b0), "r"(b1));
            }
        }
    }

    // ---- phase 3: epilogue bias + relu ----
    #pragma unroll
    for (int ni = 0; ni < 8; ni++) {
        int col = warp_n * 64 + ni * 8 + 2 * tg;
        float b0 = bias[col], b1 = bias[col + 1];
        #pragma unroll
        for (int mi = 0; mi < 2; mi++) {
            int row = m0 + warp_m * 32 + mi * 16 + g;
            if (row < NN) {
                float2 r0;
                r0.x = fmaxf(acc[mi][ni][0] + b0, 0.f);
                r0.y = fmaxf(acc[mi][ni][1] + b1, 0.f);
                *(float2*)&hout[(size_t)row * DD + col] = r0;
            }
            if (row + 8 < NN) {
                float2 r1;
                r1.x = fmaxf(acc[mi][ni][2] + b0, 0.f);
                r1.y = fmaxf(acc[mi][ni][3] + b1, 0.f);
                *(float2*)&hout[(size_t)(row + 8) * DD + col] = r1;
            }
        }
    }
}

// ---------------- launcher ----------------
extern "C" void kernel_launch(void* const* d_in, const int* in_sizes, int n_in,
                              void* d_out, int out_size) {
    const int*   ann = (const int*)d_in[0];
    const int*   src = (const int*)d_in[1];
    const int*   dst = (const int*)d_in[2];
    const float* emb = (const float*)d_in[3];
    const float* Ws  = (const float*)d_in[4];
    const float* bs  = (const float*)d_in[5];
    float*       out = (float*)d_out;

    cudaFuncSetAttribute(k_layer, cudaFuncAttributeMaxDynamicSharedMemorySize, LSMEM);

    k_init   <<<(NN * 32 + 255) / 256, 256>>>(ann, emb);
    k_count  <<<(NE + 255) / 256, 256>>>(dst);
    k_scan   <<<1, 1024>>>();
    k_scatter<<<(NE + 255) / 256, 256>>>(src, dst);

    float* hA; float* hB;
    cudaGetSymbolAddress((void**)&hA, g_hA);
    cudaGetSymbolAddress((void**)&hB, g_hB);

    int grid = (NN + 127) / 128;  // 782
    k_layer<<<grid, 256, LSMEM>>>(hA, hB, Ws + 0 * DD * DD, bs + 0 * DD);
    k_layer<<<grid, 256, LSMEM>>>(hB, hA, Ws + 1 * DD * DD, bs + 1 * DD);
    k_layer<<<grid, 256, LSMEM>>>(hA, out, Ws + 2 * DD * DD, bs + 2 * DD);
}

// round 3
// speedup vs baseline: 1.5568x; 1.5568x over previous
#include <cuda_runtime.h>
#include <cuda_bf16.h>
#include <cstdint>

#define NN 100000
#define NE 1600000
#define DD 128
#define LL 3

// ---------------- device scratch ----------------
__device__ float    g_hA[(size_t)NN * DD];
__device__ float    g_hB[(size_t)NN * DD];
__device__ uint32_t g_S[(size_t)NN * DD];   // aggregated features, tf32 bit pattern
__device__ float    g_inv[NN];
__device__ int      g_deg[NN];
__device__ int      g_off[NN + 1];
__device__ int      g_cur[NN];
__device__ int      g_csr[NE];

__device__ __forceinline__ uint32_t f2tf32(float f) {
    uint32_t u;
    asm("cvt.rna.tf32.f32 %0, %1;" : "=r"(u) : "f"(f));
    return u;
}

// ---------------- setup: hA = emb[annotation], zero deg ----------------
__global__ void k_init(const int* __restrict__ ann, const float* __restrict__ emb) {
    int t = blockIdx.x * blockDim.x + threadIdx.x;
    if (t < NN * 32) {
        int v = t >> 5, lane = t & 31;
        int a = ann[v];
        ((float4*)g_hA)[t] = ((const float4*)emb)[(size_t)a * 32 + lane];
    }
    if (t < NN) g_deg[t] = 0;
}

// ---------------- degree count ----------------
__global__ void k_count(const int* __restrict__ dst) {
    int e = blockIdx.x * blockDim.x + threadIdx.x;
    if (e < NE) atomicAdd(&g_deg[dst[e]], 1);
}

// ---------------- single-block scan: range-per-thread + shuffle scan ----------------
__global__ void __launch_bounds__(1024) k_scan() {
    const int PER = (NN + 1023) / 1024;     // 98
    int t = threadIdx.x;
    int lo = t * PER;
    int hi = lo + PER; if (hi > NN) hi = NN;
    int s = 0;
    for (int i = lo; i < hi; i++) s += g_deg[i];

    int lane = t & 31, w = t >> 5;
    int v = s;
    #pragma unroll
    for (int o = 1; o < 32; o <<= 1) {
        int u = __shfl_up_sync(0xffffffffu, v, o);
        if (lane >= o) v += u;
    }
    __shared__ int ws[32];
    if (lane == 31) ws[w] = v;
    __syncthreads();
    if (w == 0) {
        int x = ws[lane];
        #pragma unroll
        for (int o = 1; o < 32; o <<= 1) {
            int u = __shfl_up_sync(0xffffffffu, x, o);
            if (lane >= o) x += u;
        }
        ws[lane] = x;
    }
    __syncthreads();
    int ex = v - s + (w > 0 ? ws[w - 1] : 0);

    int run = ex;
    for (int i = lo; i < hi; i++) {
        int d = g_deg[i];
        g_off[i] = run;
        g_cur[i] = run;
        g_inv[i] = 1.0f / (float)(d + 1);
        run += d;
    }
    if (hi == NN && lo < NN) g_off[NN] = run;
}

// ---------------- scatter edges into CSR ----------------
__global__ void k_scatter(const int* __restrict__ src, const int* __restrict__ dst) {
    int e = blockIdx.x * blockDim.x + threadIdx.x;
    if (e < NE) {
        int d = dst[e];
        int p = atomicAdd(&g_cur[d], 1);
        g_csr[p] = src[e];
    }
}

// ---------------- SAGE aggregation: warp per node, writes tf32 bits ----------------
__global__ void __launch_bounds__(256) k_sage(const float* __restrict__ hin) {
    int gt = blockIdx.x * blockDim.x + threadIdx.x;
    int v = gt >> 5;
    if (v >= NN) return;
    int lane = gt & 31;
    const float4* h4 = (const float4*)hin;
    float4 acc = h4[(size_t)v * 32 + lane];
    int s = g_off[v], e = g_off[v + 1];
    for (int i = s; i < e; i++) {
        int u = __ldg(&g_csr[i]);
        float4 x = h4[(size_t)u * 32 + lane];
        acc.x += x.x; acc.y += x.y; acc.z += x.z; acc.w += x.w;
    }
    float iv = g_inv[v];
    uint4 r;
    r.x = f2tf32(acc.x * iv); r.y = f2tf32(acc.y * iv);
    r.z = f2tf32(acc.z * iv); r.w = f2tf32(acc.w * iv);
    ((uint4*)g_S)[(size_t)v * 32 + lane] = r;
}

// ---------------- tf32 MMA GEMM: hout = relu(S @ W + b) ----------------
#define APITCH 132   // bank = (4r + c) & 31 -> conflict-free A-fragment reads
#define BPITCH 136   // bank = (8k + n) & 31 -> conflict-free B-fragment reads
#define GSMEM ((128 * APITCH + 128 * BPITCH) * 4)

__global__ void __launch_bounds__(256) k_mma(float* __restrict__ hout,
                                             const float* __restrict__ W,
                                             const float* __restrict__ bias) {
    extern __shared__ uint32_t sm[];
    uint32_t* As = sm;                 // [128][APITCH]
    uint32_t* Bs = sm + 128 * APITCH;  // [128][BPITCH], Bs[k][n]
    int tid = threadIdx.x;
    int lane = tid & 31, w = tid >> 5;
    int m0 = blockIdx.x * 128;

    // load A (tf32 bits from g_S) and B (convert W)
    #pragma unroll
    for (int t = 0; t < 16; t++) {
        int q = tid + t * 256;            // 0..4095 vec4 index
        int r = q >> 5, c4 = (q & 31) * 4;
        uint4 av;
        if (m0 + r < NN) av = ((const uint4*)g_S)[(size_t)(m0 + r) * 32 + (q & 31)];
        else             av = make_uint4(0u, 0u, 0u, 0u);
        *(uint4*)&As[r * APITCH + c4] = av;
        float4 wv = ((const float4*)W)[q];
        uint32_t* p = &Bs[r * BPITCH + c4];
        p[0] = f2tf32(wv.x); p[1] = f2tf32(wv.y); p[2] = f2tf32(wv.z); p[3] = f2tf32(wv.w);
    }
    __syncthreads();

    // warp tile: 32(M) x 64(N)
    int warp_m = w >> 1;
    int warp_n = w & 1;
    int g = lane >> 2;            // 0..7
    int tg = lane & 3;            // 0..3

    float acc[2][8][4];
    #pragma unroll
    for (int mi = 0; mi < 2; mi++)
        #pragma unroll
        for (int ni = 0; ni < 8; ni++)
            #pragma unroll
            for (int c = 0; c < 4; c++) acc[mi][ni][c] = 0.f;

    #pragma unroll
    for (int kc = 0; kc < 16; kc++) {
        int k0 = kc * 8;
        uint32_t a[2][4];
        #pragma unroll
        for (int mi = 0; mi < 2; mi++) {
            int r = warp_m * 32 + mi * 16 + g;
            a[mi][0] = As[r * APITCH + k0 + tg];
            a[mi][1] = As[(r + 8) * APITCH + k0 + tg];
            a[mi][2] = As[r * APITCH + k0 + tg + 4];
            a[mi][3] = As[(r + 8) * APITCH + k0 + tg + 4];
        }
        #pragma unroll
        for (int ni = 0; ni < 8; ni++) {
            int cn = warp_n * 64 + ni * 8 + g;
            uint32_t b0 = Bs[(k0 + tg) * BPITCH + cn];
            uint32_t b1 = Bs[(k0 + tg + 4) * BPITCH + cn];
            #pragma unroll
            for (int mi = 0; mi < 2; mi++) {
                asm volatile(
                    "mma.sync.aligned.m16n8k8.row.col.f32.tf32.tf32.f32 "
                    "{%0,%1,%2,%3}, {%4,%5,%6,%7}, {%8,%9}, {%0,%1,%2,%3};"
                    : "+f"(acc[mi][ni][0]), "+f"(acc[mi][ni][1]),
                      "+f"(acc[mi][ni][2]), "+f"(acc[mi][ni][3])
                    : "r"(a[mi][0]), "r"(a[mi][1]), "r"(a[mi][2]), "r"(a[mi][3]),
                      "r"(b0), "r"(b1));
            }
        }
    }

    // epilogue: bias + relu
    #pragma unroll
    for (int ni = 0; ni < 8; ni++) {
        int col = warp_n * 64 + ni * 8 + 2 * tg;
        float b0 = bias[col], b1 = bias[col + 1];
        #pragma unroll
        for (int mi = 0; mi < 2; mi++) {
            int row = m0 + warp_m * 32 + mi * 16 + g;
            if (row < NN) {
                float2 r0;
                r0.x = fmaxf(acc[mi][ni][0] + b0, 0.f);
                r0.y = fmaxf(acc[mi][ni][1] + b1, 0.f);
                *(float2*)&hout[(size_t)row * DD + col] = r0;
            }
            if (row + 8 < NN) {
                float2 r1;
                r1.x = fmaxf(acc[mi][ni][2] + b0, 0.f);
                r1.y = fmaxf(acc[mi][ni][3] + b1, 0.f);
                *(float2*)&hout[(size_t)(row + 8) * DD + col] = r1;
            }
        }
    }
}

// ---------------- launcher ----------------
extern "C" void kernel_launch(void* const* d_in, const int* in_sizes, int n_in,
                              void* d_out, int out_size) {
    const int*   ann = (const int*)d_in[0];
    const int*   src = (const int*)d_in[1];
    const int*   dst = (const int*)d_in[2];
    const float* emb = (const float*)d_in[3];
    const float* Ws  = (const float*)d_in[4];
    const float* bs  = (const float*)d_in[5];
    float*       out = (float*)d_out;

    cudaFuncSetAttribute(k_mma, cudaFuncAttributeMaxDynamicSharedMemorySize, GSMEM);

    k_init   <<<(NN * 32 + 255) / 256, 256>>>(ann, emb);
    k_count  <<<(NE + 255) / 256, 256>>>(dst);
    k_scan   <<<1, 1024>>>();
    k_scatter<<<(NE + 255) / 256, 256>>>(src, dst);

    float* hA; float* hB;
    cudaGetSymbolAddress((void**)&hA, g_hA);
    cudaGetSymbolAddress((void**)&hB, g_hB);

    int grid = (NN + 127) / 128;  // 782
    k_sage<<<(NN * 32 + 255) / 256, 256>>>(hA);
    k_mma <<<grid, 256, GSMEM>>>(hB, Ws + 0 * DD * DD, bs + 0 * DD);
    k_sage<<<(NN * 32 + 255) / 256, 256>>>(hB);
    k_mma <<<grid, 256, GSMEM>>>(hA, Ws + 1 * DD * DD, bs + 1 * DD);
    k_sage<<<(NN * 32 + 255) / 256, 256>>>(hA);
    k_mma <<<grid, 256, GSMEM>>>(out, Ws + 2 * DD * DD, bs + 2 * DD);
}

// round 4
// speedup vs baseline: 1.6371x; 1.0516x over previous
#include <cuda_runtime.h>
#include <cuda_fp16.h>
#include <cstdint>

#define NN 100000
#define NE 1600000
#define DD 128
#define LL 3

// ---------------- device scratch ----------------
__device__ __half   g_hA[(size_t)NN * DD];
__device__ __half   g_hB[(size_t)NN * DD];
__device__ uint32_t g_S[(size_t)NN * DD];   // aggregated features, tf32 bit pattern
__device__ float    g_inv[NN];
__device__ int      g_deg[NN];
__device__ int      g_off[NN + 1];
__device__ int      g_cur[NN];
__device__ int      g_csr[NE];

__device__ __forceinline__ uint32_t f2tf32(float f) {
    uint32_t u;
    asm("cvt.rna.tf32.f32 %0, %1;" : "=r"(u) : "f"(f));
    return u;
}

// ---------------- setup: hA = (half)emb[annotation], zero deg ----------------
__global__ void k_init(const int* __restrict__ ann, const float* __restrict__ emb) {
    int t = blockIdx.x * blockDim.x + threadIdx.x;
    if (t < NN * 32) {
        int v = t >> 5, q = t & 31;          // q indexes 4-elem chunks
        int a = ann[v];
        float4 val = ((const float4*)emb)[(size_t)a * 32 + q];
        uint2 o;
        __half2 h01 = __floats2half2_rn(val.x, val.y);
        __half2 h23 = __floats2half2_rn(val.z, val.w);
        o.x = *(uint32_t*)&h01; o.y = *(uint32_t*)&h23;
        ((uint2*)g_hA)[t] = o;
    }
    if (t < NN) g_deg[t] = 0;
}

// ---------------- degree count ----------------
__global__ void k_count(const int* __restrict__ dst) {
    int e = blockIdx.x * blockDim.x + threadIdx.x;
    if (e < NE) atomicAdd(&g_deg[dst[e]], 1);
}

// ---------------- single-block scan: range-per-thread + shuffle scan ----------------
__global__ void __launch_bounds__(1024) k_scan() {
    const int PER = (NN + 1023) / 1024;     // 98
    int t = threadIdx.x;
    int lo = t * PER;
    int hi = lo + PER; if (hi > NN) hi = NN;
    int s = 0;
    for (int i = lo; i < hi; i++) s += g_deg[i];

    int lane = t & 31, w = t >> 5;
    int v = s;
    #pragma unroll
    for (int o = 1; o < 32; o <<= 1) {
        int u = __shfl_up_sync(0xffffffffu, v, o);
        if (lane >= o) v += u;
    }
    __shared__ int ws[32];
    if (lane == 31) ws[w] = v;
    __syncthreads();
    if (w == 0) {
        int x = ws[lane];
        #pragma unroll
        for (int o = 1; o < 32; o <<= 1) {
            int u = __shfl_up_sync(0xffffffffu, x, o);
            if (lane >= o) x += u;
        }
        ws[lane] = x;
    }
    __syncthreads();
    int ex = v - s + (w > 0 ? ws[w - 1] : 0);

    int run = ex;
    for (int i = lo; i < hi; i++) {
        int d = g_deg[i];
        g_off[i] = run;
        g_cur[i] = run;
        g_inv[i] = 1.0f / (float)(d + 1);
        run += d;
    }
    if (hi == NN && lo < NN) g_off[NN] = run;
}

// ---------------- scatter edges into CSR ----------------
__global__ void k_scatter(const int* __restrict__ src, const int* __restrict__ dst) {
    int e = blockIdx.x * blockDim.x + threadIdx.x;
    if (e < NE) {
        int d = dst[e];
        int p = atomicAdd(&g_cur[d], 1);
        g_csr[p] = src[e];
    }
}

// ---------------- SAGE aggregation: warp per node, fp16 gather -> tf32 bits ----------------
__global__ void __launch_bounds__(256) k_sage(const __half* __restrict__ hin) {
    int gt = blockIdx.x * blockDim.x + threadIdx.x;
    int v = gt >> 5;
    if (v >= NN) return;
    int lane = gt & 31;
    const uint2* h2 = (const uint2*)hin;    // 4 halves per uint2, 32 per row

    uint2 sv = h2[(size_t)v * 32 + lane];   // self term
    float2 f01 = __half22float2(*(__half2*)&sv.x);
    float2 f23 = __half22float2(*(__half2*)&sv.y);
    float4 acc = make_float4(f01.x, f01.y, f23.x, f23.y);

    int s = g_off[v], e = g_off[v + 1];
    for (int i = s; i < e; i++) {
        int u = __ldg(&g_csr[i]);
        uint2 xv = h2[(size_t)u * 32 + lane];
        float2 x01 = __half22float2(*(__half2*)&xv.x);
        float2 x23 = __half22float2(*(__half2*)&xv.y);
        acc.x += x01.x; acc.y += x01.y; acc.z += x23.x; acc.w += x23.y;
    }
    float iv = g_inv[v];
    uint4 r;
    r.x = f2tf32(acc.x * iv); r.y = f2tf32(acc.y * iv);
    r.z = f2tf32(acc.z * iv); r.w = f2tf32(acc.w * iv);
    ((uint4*)g_S)[(size_t)v * 32 + lane] = r;
}

// ---------------- tf32 MMA GEMM: hout = relu(S @ W + b) ----------------
#define APITCH 132   // bank = (4r + c) & 31 -> conflict-free A-fragment reads
#define BPITCH 136   // bank = (8k + n) & 31 -> conflict-free B-fragment reads
#define GSMEM ((128 * APITCH + 128 * BPITCH) * 4)

__global__ void __launch_bounds__(256) k_mma(__half* __restrict__ hout_h,
                                             float* __restrict__ out_f,
                                             const float* __restrict__ W,
                                             const float* __restrict__ bias) {
    extern __shared__ uint32_t sm[];
    uint32_t* As = sm;                 // [128][APITCH]
    uint32_t* Bs = sm + 128 * APITCH;  // [128][BPITCH], Bs[k][n]
    int tid = threadIdx.x;
    int lane = tid & 31, w = tid >> 5;
    int m0 = blockIdx.x * 128;

    #pragma unroll
    for (int t = 0; t < 16; t++) {
        int q = tid + t * 256;            // 0..4095 vec4 index
        int r = q >> 5, c4 = (q & 31) * 4;
        uint4 av;
        if (m0 + r < NN) av = ((const uint4*)g_S)[(size_t)(m0 + r) * 32 + (q & 31)];
        else             av = make_uint4(0u, 0u, 0u, 0u);
        *(uint4*)&As[r * APITCH + c4] = av;
        float4 wv = ((const float4*)W)[q];
        uint32_t* p = &Bs[r * BPITCH + c4];
        p[0] = f2tf32(wv.x); p[1] = f2tf32(wv.y); p[2] = f2tf32(wv.z); p[3] = f2tf32(wv.w);
    }
    __syncthreads();

    int warp_m = w >> 1;
    int warp_n = w & 1;
    int g = lane >> 2;            // 0..7
    int tg = lane & 3;            // 0..3

    float acc[2][8][4];
    #pragma unroll
    for (int mi = 0; mi < 2; mi++)
        #pragma unroll
        for (int ni = 0; ni < 8; ni++)
            #pragma unroll
            for (int c = 0; c < 4; c++) acc[mi][ni][c] = 0.f;

    #pragma unroll
    for (int kc = 0; kc < 16; kc++) {
        int k0 = kc * 8;
        uint32_t a[2][4];
        #pragma unroll
        for (int mi = 0; mi < 2; mi++) {
            int r = warp_m * 32 + mi * 16 + g;
            a[mi][0] = As[r * APITCH + k0 + tg];
            a[mi][1] = As[(r + 8) * APITCH + k0 + tg];
            a[mi][2] = As[r * APITCH + k0 + tg + 4];
            a[mi][3] = As[(r + 8) * APITCH + k0 + tg + 4];
        }
        #pragma unroll
        for (int ni = 0; ni < 8; ni++) {
            int cn = warp_n * 64 + ni * 8 + g;
            uint32_t b0 = Bs[(k0 + tg) * BPITCH + cn];
            uint32_t b1 = Bs[(k0 + tg + 4) * BPITCH + cn];
            #pragma unroll
            for (int mi = 0; mi < 2; mi++) {
                asm volatile(
                    "mma.sync.aligned.m16n8k8.row.col.f32.tf32.tf32.f32 "
                    "{%0,%1,%2,%3}, {%4,%5,%6,%7}, {%8,%9}, {%0,%1,%2,%3};"
                    : "+f"(acc[mi][ni][0]), "+f"(acc[mi][ni][1]),
                      "+f"(acc[mi][ni][2]), "+f"(acc[mi][ni][3])
                    : "r"(a[mi][0]), "r"(a[mi][1]), "r"(a[mi][2]), "r"(a[mi][3]),
                      "r"(b0), "r"(b1));
            }
        }
    }

    // epilogue: bias + relu; half for inter-layer, float for final
    #pragma unroll
    for (int ni = 0; ni < 8; ni++) {
        int col = warp_n * 64 + ni * 8 + 2 * tg;
        float b0 = bias[col], b1 = bias[col + 1];
        #pragma unroll
        for (int mi = 0; mi < 2; mi++) {
            int row = m0 + warp_m * 32 + mi * 16 + g;
            float v00 = fmaxf(acc[mi][ni][0] + b0, 0.f);
            float v01 = fmaxf(acc[mi][ni][1] + b1, 0.f);
            float v10 = fmaxf(acc[mi][ni][2] + b0, 0.f);
            float v11 = fmaxf(acc[mi][ni][3] + b1, 0.f);
            if (out_f) {
                if (row < NN)     { float2 r0 = {v00, v01}; *(float2*)&out_f[(size_t)row * DD + col] = r0; }
                if (row + 8 < NN) { float2 r1 = {v10, v11}; *(float2*)&out_f[(size_t)(row + 8) * DD + col] = r1; }
            } else {
                if (row < NN)     *(__half2*)&hout_h[(size_t)row * DD + col] = __floats2half2_rn(v00, v01);
                if (row + 8 < NN) *(__half2*)&hout_h[(size_t)(row + 8) * DD + col] = __floats2half2_rn(v10, v11);
            }
        }
    }
}

// ---------------- launcher ----------------
extern "C" void kernel_launch(void* const* d_in, const int* in_sizes, int n_in,
                              void* d_out, int out_size) {
    const int*   ann = (const int*)d_in[0];
    const int*   src = (const int*)d_in[1];
    const int*   dst = (const int*)d_in[2];
    const float* emb = (const float*)d_in[3];
    const float* Ws  = (const float*)d_in[4];
    const float* bs  = (const float*)d_in[5];
    float*       out = (float*)d_out;

    cudaFuncSetAttribute(k_mma, cudaFuncAttributeMaxDynamicSharedMemorySize, GSMEM);

    k_init   <<<(NN * 32 + 255) / 256, 256>>>(ann, emb);
    k_count  <<<(NE + 255) / 256, 256>>>(dst);
    k_scan   <<<1, 1024>>>();
    k_scatter<<<(NE + 255) / 256, 256>>>(src, dst);

    __half* hA; __half* hB;
    cudaGetSymbolAddress((void**)&hA, g_hA);
    cudaGetSymbolAddress((void**)&hB, g_hB);

    int grid = (NN + 127) / 128;  // 782
    k_sage<<<(NN * 32 + 255) / 256, 256>>>(hA);
    k_mma <<<grid, 256, GSMEM>>>(hB, nullptr, Ws + 0 * DD * DD, bs + 0 * DD);
    k_sage<<<(NN * 32 + 255) / 256, 256>>>(hB);
    k_mma <<<grid, 256, GSMEM>>>(hA, nullptr, Ws + 1 * DD * DD, bs + 1 * DD);
    k_sage<<<(NN * 32 + 255) / 256, 256>>>(hA);
    k_mma <<<grid, 256, GSMEM>>>(nullptr, out, Ws + 2 * DD * DD, bs + 2 * DD);
}